// round 8
// baseline (speedup 1.0000x reference)
#include <cuda_runtime.h>
#include <cuda_bf16.h>

// DCTExtractor: gray = 0.299R+0.587G+0.114B, per-8x8-block 2D DCT
// (D @ blk @ D^T) * mask -> (B,1,H,W).
//
// 8 lanes per block, warp = 4 horizontally-adjacent blocks.
// Lane owns one block COLUMN: 24 independent scalar LDG (front-batched,
// 128B/warp-instr coalesced). Stage 1 in-lane, one shfl_xor 8x8 transpose,
// stage 2 in-lane, smem-staged coalesced stores. ~60 regs -> 32+ warps/SM.

#define TPB 256

__global__ __launch_bounds__(TPB, 4)
void dct_extract_kernel(const float* __restrict__ x,
                        const float* __restrict__ dctm,
                        const float* __restrict__ mask,
                        float* __restrict__ out,
                        int nblocks)
{
    __shared__ float Ds[64];
    __shared__ float Msk[64];
    __shared__ float St[8][8][36];   // [warp][tile row][32 cols + 4 pad] = 9216 B

    const int t = threadIdx.x;
    if (t < 64)       Ds[t]       = dctm[t];
    else if (t < 128) Msk[t - 64] = mask[t - 64];
    __syncthreads();

    const int W  = 512;
    const int HW = 512 * 512;
    const int warp = t >> 5;
    const int lane = t & 31;
    const int grp  = lane >> 3;   // which of the 4 blocks
    const int r8   = lane & 7;    // index within 8-lane group

    // warp's first block (4 consecutive bx; 4 | 64 so never wraps a row)
    const int wblk = (blockIdx.x * 8 + warp) * 4;
    if (wblk >= nblocks) return;  // warp-uniform

    const int b   = wblk >> 12;          // 4096 blocks per image
    const int rr  = wblk & 4095;
    const int by  = rr >> 6;
    const int bx0 = rr & 63;

    // lane l reads global column bx0*8 + l  -> 32 consecutive floats per LDG
    const float* base = x + (size_t)b * 3 * HW + (size_t)(by * 8) * W
                          + bx0 * 8 + lane;

    // ---- 24 independent loads, fused grayscale: v[k] = column value row k ----
    float v[8];
#pragma unroll
    for (int k = 0; k < 8; ++k) {
        const float rc = base[k * W];
        const float gc = base[HW + k * W];
        const float bc = base[2 * HW + k * W];
        v[k] = fmaf(0.114f, bc, fmaf(0.587f, gc, 0.299f * rc));
    }

    // ---- stage 1 (in-lane): tm[i] = (D @ blk)[i][mycol] ----
    float tm[8];
#pragma unroll
    for (int i = 0; i < 8; ++i) {
        float s = Ds[i * 8] * v[0];
#pragma unroll
        for (int k = 1; k < 8; ++k)
            s = fmaf(Ds[i * 8 + k], v[k], s);
        tm[i] = s;
    }

    // ---- 8x8 register transpose across the 8-lane group (xor butterfly) ----
#pragma unroll
    for (int s = 1; s < 8; s <<= 1) {
        const bool up = (lane & s);
#pragma unroll
        for (int i = 0; i < 8; ++i) {
            if ((i & s) == 0) {
                const float a  = up ? tm[i] : tm[i | s];
                const float xc = __shfl_xor_sync(0xFFFFFFFFu, a, s);
                if (up) tm[i] = xc; else tm[i | s] = xc;
            }
        }
    }
    // lane now holds row r8 of M = D @ blk (for its block)

    // ---- stage 2 (in-lane): o[j] = (M @ D^T)[r8][j] * mask[r8][j] ----
    float o[8];
#pragma unroll
    for (int j = 0; j < 8; ++j) {
        float s = tm[0] * Ds[j * 8];
#pragma unroll
        for (int k = 1; k < 8; ++k)
            s = fmaf(tm[k], Ds[j * 8 + k], s);
        o[j] = s * Msk[r8 * 8 + j];
    }

    // ---- stage rows into smem (conflict-free via 36-float row stride) ----
    float* sp = &St[warp][r8][grp * 8];
    *(float4*)sp       = make_float4(o[0], o[1], o[2], o[3]);
    *(float4*)(sp + 4) = make_float4(o[4], o[5], o[6], o[7]);
    __syncwarp();

    // ---- coalesced store: each instr writes 4 full 128B tile rows ----
    float* ob = out + (size_t)b * HW + (size_t)(by * 8) * W + bx0 * 8;
    {
        const int row = lane >> 3;   // 0..3
        const int ch  = lane & 7;    // 16B chunk within the 128B row
        const float4 d0 = *(const float4*)&St[warp][row][ch * 4];
        const float4 d1 = *(const float4*)&St[warp][row + 4][ch * 4];
        *(float4*)(ob + row * W + ch * 4)       = d0;
        *(float4*)(ob + (row + 4) * W + ch * 4) = d1;
    }
}

extern "C" void kernel_launch(void* const* d_in, const int* in_sizes, int n_in,
                              void* d_out, int out_size)
{
    const float* x    = (const float*)d_in[0];
    const float* dctm = (const float*)d_in[1];
    const float* mask = (const float*)d_in[2];
    float* out        = (float*)d_out;

    const int HW = 512 * 512;
    const int B  = in_sizes[0] / (3 * HW);   // 64
    const int nblocks = B * 64 * 64;         // 262144 8x8 blocks

    // 32 blocks per CTA (8 warps x 4 blocks)
    const int grid = (nblocks + 31) / 32;    // 8192
    dct_extract_kernel<<<grid, TPB>>>(x, dctm, mask, out, nblocks);
}

// round 9
// speedup vs baseline: 1.2457x; 1.2457x over previous
#include <cuda_runtime.h>
#include <cuda_bf16.h>

// DCTExtractor: gray = 0.299R + 0.587G + 0.114B, per-8x8-block 2D DCT
// (D @ blk @ D^T) * mask, folded back to (B,1,H,W).
//
// One thread owns one 8x8 block entirely in registers (R2 structure — best
// measured). TPB=64 / launch_bounds(64,8): same 128-reg budget and 16
// warps/SM as the 42.1us R2 kernel, but 4x finer wave quanta -> the partial
// final wave wastes ~1/4 as much time. Each CTA = one block-row of one image.

#define TPB 64

__global__ __launch_bounds__(TPB, 8)
void dct_extract_kernel(const float* __restrict__ x,
                        const float* __restrict__ dctm,
                        const float* __restrict__ mask,
                        float* __restrict__ out,
                        int total)
{
    __shared__ float Ds[64];
    __shared__ float Ms[64];
    const int t = threadIdx.x;
    Ds[t] = dctm[t];
    Ms[t] = mask[t];
    __syncthreads();

    const int gid = blockIdx.x * TPB + t;
    if (gid >= total) return;

    const int W  = 512;
    const int HW = 512 * 512;

    // gid -> (batch, block_y, block_x); nh = nw = 64 -> 4096 blocks/image
    const int b  = gid >> 12;
    const int rr = gid & 4095;
    const int by = rr >> 6;
    const int bx = rr & 63;

    const float* p0 = x + (size_t)b * 3 * HW + (size_t)(by * 8) * W + bx * 8;

    // ---- load 8x8 grayscale block into registers (float4, fully coalesced) ----
    float g[8][8];
#pragma unroll
    for (int j = 0; j < 8; ++j) {
        const float* row = p0 + j * W;
        const float4 r0 = *(const float4*)(row);
        const float4 r1 = *(const float4*)(row + 4);
        const float4 g0 = *(const float4*)(row + HW);
        const float4 g1 = *(const float4*)(row + HW + 4);
        const float4 b0 = *(const float4*)(row + 2 * HW);
        const float4 b1 = *(const float4*)(row + 2 * HW + 4);
        g[j][0] = fmaf(0.114f, b0.x, fmaf(0.587f, g0.x, 0.299f * r0.x));
        g[j][1] = fmaf(0.114f, b0.y, fmaf(0.587f, g0.y, 0.299f * r0.y));
        g[j][2] = fmaf(0.114f, b0.z, fmaf(0.587f, g0.z, 0.299f * r0.z));
        g[j][3] = fmaf(0.114f, b0.w, fmaf(0.587f, g0.w, 0.299f * r0.w));
        g[j][4] = fmaf(0.114f, b1.x, fmaf(0.587f, g1.x, 0.299f * r1.x));
        g[j][5] = fmaf(0.114f, b1.y, fmaf(0.587f, g1.y, 0.299f * r1.y));
        g[j][6] = fmaf(0.114f, b1.z, fmaf(0.587f, g1.z, 0.299f * r1.z));
        g[j][7] = fmaf(0.114f, b1.w, fmaf(0.587f, g1.w, 0.299f * r1.w));
    }

    // ---- separable DCT, one output row at a time: out[i][:] = (D[i,:] @ g) @ D^T ----
    float* po = out + (size_t)b * HW + (size_t)(by * 8) * W + bx * 8;

#pragma unroll
    for (int i = 0; i < 8; ++i) {
        // temp row: tr[k] = sum_j D[i][j] * g[j][k]
        float tr[8];
#pragma unroll
        for (int k = 0; k < 8; ++k) {
            float s = Ds[i * 8 + 0] * g[0][k];
#pragma unroll
            for (int j = 1; j < 8; ++j)
                s = fmaf(Ds[i * 8 + j], g[j][k], s);
            tr[k] = s;
        }
        // out row: o[l] = (sum_k tr[k] * D[l][k]) * mask[i][l]
        float o[8];
#pragma unroll
        for (int l = 0; l < 8; ++l) {
            float s = tr[0] * Ds[l * 8 + 0];
#pragma unroll
            for (int k = 1; k < 8; ++k)
                s = fmaf(tr[k], Ds[l * 8 + k], s);
            o[l] = s * Ms[i * 8 + l];
        }
        float* row = po + i * W;
        *(float4*)(row)     = make_float4(o[0], o[1], o[2], o[3]);
        *(float4*)(row + 4) = make_float4(o[4], o[5], o[6], o[7]);
    }
}

extern "C" void kernel_launch(void* const* d_in, const int* in_sizes, int n_in,
                              void* d_out, int out_size)
{
    const float* x    = (const float*)d_in[0];
    const float* dctm = (const float*)d_in[1];
    const float* mask = (const float*)d_in[2];
    float* out        = (float*)d_out;

    const int HW = 512 * 512;
    const int B  = in_sizes[0] / (3 * HW);      // 64
    const int total = B * 64 * 64;              // one thread per 8x8 block

    const int grid = (total + TPB - 1) / TPB;   // 4096; one block-row per CTA
    dct_extract_kernel<<<grid, TPB>>>(x, dctm, mask, out, total);
}